// round 1
// baseline (speedup 1.0000x reference)
#include <cuda_runtime.h>
#include <cstdint>

// ============================================================================
// Monte-Carlo E[softmax(mean + eps)], eps ~ N(0, diag(var)), 400 samples.
// Bit-compatible with JAX threefry2x32 (partitionable=True path):
//   subkey_s = threefry2x32((0,42), (0, s))            (both outputs)
//   bits_i   = v0 ^ v1 of threefry2x32(subkey_s, (0, i))
//   u        = max(lo, ((bits>>9)|0x3F800000 - 1.0f) * 2.0f + lo),
//              lo = nextafter(-1,0)
//   eps      = sqrt(2) * erfinv_xla(u) * sqrt(var)
// softmax computed without max-subtraction (value-identical).
// One warp per row; 16 elements per lane; everything register-resident.
// ============================================================================

#define NROWS 16384
#define NCOLS 512
#define WARPS_PER_BLOCK 8
#define NTHREADS (WARPS_PER_BLOCK * 32)
#define KPL 16  // NCOLS / 32 elements per lane
#define MAX_SAMPLES 1024

__device__ __forceinline__ void tf_round(uint32_t& x0, uint32_t& x1, int r) {
    x0 += x1;
    x1 = __funnelshift_l(x1, x1, r);  // rotl32
    x1 ^= x0;
}

__device__ __forceinline__ uint2 threefry2x32(uint32_t k0, uint32_t k1,
                                              uint32_t c0, uint32_t c1) {
    uint32_t k2 = k0 ^ k1 ^ 0x1BD11BDAu;
    uint32_t x0 = c0 + k0;
    uint32_t x1 = c1 + k1;
    tf_round(x0, x1, 13); tf_round(x0, x1, 15); tf_round(x0, x1, 26); tf_round(x0, x1, 6);
    x0 += k1; x1 += k2 + 1u;
    tf_round(x0, x1, 17); tf_round(x0, x1, 29); tf_round(x0, x1, 16); tf_round(x0, x1, 24);
    x0 += k2; x1 += k0 + 2u;
    tf_round(x0, x1, 13); tf_round(x0, x1, 15); tf_round(x0, x1, 26); tf_round(x0, x1, 6);
    x0 += k0; x1 += k1 + 3u;
    tf_round(x0, x1, 17); tf_round(x0, x1, 29); tf_round(x0, x1, 16); tf_round(x0, x1, 24);
    x0 += k1; x1 += k2 + 4u;
    tf_round(x0, x1, 13); tf_round(x0, x1, 15); tf_round(x0, x1, 26); tf_round(x0, x1, 6);
    x0 += k2; x1 += k0 + 5u;
    return make_uint2(x0, x1);
}

// XLA ErfInv 32-bit (Giles), returns erfinv(x) (sqrt(2) folded by caller).
__device__ __forceinline__ float erfinv_xla(float x) {
    float t = fmaf(-x, x, 1.0f);            // 1 - x^2
    float lg;
    asm("lg2.approx.f32 %0, %1;" : "=f"(lg) : "f"(t));
    float w = -0.6931471805599453f * lg;    // -ln(1-x^2)
    float p;
    if (w < 5.0f) {
        w -= 2.5f;
        p = 2.81022636e-08f;
        p = fmaf(p, w, 3.43273939e-07f);
        p = fmaf(p, w, -3.5233877e-06f);
        p = fmaf(p, w, -4.39150654e-06f);
        p = fmaf(p, w, 0.00021858087f);
        p = fmaf(p, w, -0.00125372503f);
        p = fmaf(p, w, -0.00417768164f);
        p = fmaf(p, w, 0.246640727f);
        p = fmaf(p, w, 1.50140941f);
    } else {
        float sw;
        asm("sqrt.approx.f32 %0, %1;" : "=f"(sw) : "f"(w));
        w = sw - 3.0f;
        p = -0.000200214257f;
        p = fmaf(p, w, 0.000100950558f);
        p = fmaf(p, w, 0.00134934322f);
        p = fmaf(p, w, -0.00367342844f);
        p = fmaf(p, w, 0.00573950773f);
        p = fmaf(p, w, -0.0076224613f);
        p = fmaf(p, w, 0.00943887047f);
        p = fmaf(p, w, 1.00167406f);
        p = fmaf(p, w, 2.83297682f);
    }
    return p * x;
}

__global__ void __launch_bounds__(NTHREADS, 2)
mc_softmax_kernel(const float* __restrict__ mean,
                  const float* __restrict__ var,
                  const int* __restrict__ d_ns,
                  float* __restrict__ out) {
    __shared__ uint2 skeys[MAX_SAMPLES];

    int ns = d_ns ? *d_ns : 400;
    if (ns > MAX_SAMPLES) ns = MAX_SAMPLES;

    int tid = threadIdx.x;
    // Precompute per-sample subkeys: subkey_s = threefry(key, (0, s)).
    for (int s = tid; s < ns; s += NTHREADS) {
        skeys[s] = threefry2x32(0u, 42u, 0u, (uint32_t)s);
    }
    __syncthreads();

    int warp = tid >> 5;
    int lane = tid & 31;
    int row = blockIdx.x * WARPS_PER_BLOCK + warp;
    int base = row * NCOLS + lane;

    const float LOG2E = 1.4426950408889634f;
    const float S2LOG2E = 1.41421356237309504880f * 1.4426950408889634f;
    const float LO = __int_as_float(0xBF7FFFFF);  // nextafter(-1, 0)

    float m2[KPL], s3[KPL], acc[KPL];
#pragma unroll
    for (int k = 0; k < KPL; k++) {
        int i = base + 32 * k;
        m2[k] = mean[i] * LOG2E;
        s3[k] = sqrtf(var[i]) * S2LOG2E;
        acc[k] = 0.0f;
    }

    for (int s = 0; s < ns; s++) {
        uint2 key = skeys[s];
        float e[KPL];
        float part = 0.0f;
#pragma unroll
        for (int k = 0; k < KPL; k++) {
            uint32_t i = (uint32_t)(base + 32 * k);
            uint2 b = threefry2x32(key.x, key.y, 0u, i);
            uint32_t bits = b.x ^ b.y;
            float f = __uint_as_float((bits >> 9) | 0x3F800000u) - 1.0f;
            float u = fmaxf(LO, fmaf(f, 2.0f, LO));
            float g = erfinv_xla(u);
            float t = fmaf(g, s3[k], m2[k]);  // (mean + eps) * log2(e)
            float ev;
            asm("ex2.approx.f32 %0, %1;" : "=f"(ev) : "f"(t));
            e[k] = ev;
            part += ev;
        }
        // Warp allreduce: row sum of exp.
#pragma unroll
        for (int o = 16; o > 0; o >>= 1)
            part += __shfl_xor_sync(0xffffffffu, part, o);
        float rinv;
        asm("rcp.approx.f32 %0, %1;" : "=f"(rinv) : "f"(part));
#pragma unroll
        for (int k = 0; k < KPL; k++)
            acc[k] = fmaf(e[k], rinv, acc[k]);
    }

    float inv = 1.0f / (float)ns;
#pragma unroll
    for (int k = 0; k < KPL; k++)
        out[base + 32 * k] = acc[k] * inv;
}

extern "C" void kernel_launch(void* const* d_in, const int* in_sizes, int n_in,
                              void* d_out, int out_size) {
    const float* mean = (const float*)d_in[0];
    const float* var = (const float*)d_in[1];
    const int* ns = (n_in >= 3) ? (const int*)d_in[2] : nullptr;
    float* out = (float*)d_out;

    dim3 grid(NROWS / WARPS_PER_BLOCK);
    dim3 block(NTHREADS);
    mc_softmax_kernel<<<grid, block>>>(mean, var, ns, out);
}

// round 2
// speedup vs baseline: 1.0901x; 1.0901x over previous
#include <cuda_runtime.h>
#include <cstdint>

// ============================================================================
// Monte-Carlo E[softmax(mean + eps)], eps ~ N(0, diag(var)), 400 samples.
// Bit-compatible with JAX threefry2x32 (partitionable path) — confirmed R1.
// R2: pipe rebalance. Threefry round-adds forced to IMAD (fma pipe) via an
// opaque runtime `one` parameter; mantissa shift via __umulhi (fma pipe);
// redundant fmax dropped; occupancy raised to 3 CTAs/SM.
// ============================================================================

#define NROWS 16384
#define NCOLS 512
#define WARPS_PER_BLOCK 8
#define NTHREADS (WARPS_PER_BLOCK * 32)
#define KPL 16  // NCOLS / 32 elements per lane
#define MAX_SAMPLES 1024

// Compile-time-known threefry (for subkey precompute; tiny, per-block).
__device__ __forceinline__ void tf_round_c(uint32_t& x0, uint32_t& x1, int r) {
    x0 += x1;
    x1 = __funnelshift_l(x1, x1, r);
    x1 ^= x0;
}

__device__ __forceinline__ uint2 threefry2x32_c(uint32_t k0, uint32_t k1,
                                                uint32_t c0, uint32_t c1) {
    uint32_t k2 = k0 ^ k1 ^ 0x1BD11BDAu;
    uint32_t x0 = c0 + k0;
    uint32_t x1 = c1 + k1;
    tf_round_c(x0, x1, 13); tf_round_c(x0, x1, 15); tf_round_c(x0, x1, 26); tf_round_c(x0, x1, 6);
    x0 += k1; x1 += k2 + 1u;
    tf_round_c(x0, x1, 17); tf_round_c(x0, x1, 29); tf_round_c(x0, x1, 16); tf_round_c(x0, x1, 24);
    x0 += k2; x1 += k0 + 2u;
    tf_round_c(x0, x1, 13); tf_round_c(x0, x1, 15); tf_round_c(x0, x1, 26); tf_round_c(x0, x1, 6);
    x0 += k0; x1 += k1 + 3u;
    tf_round_c(x0, x1, 17); tf_round_c(x0, x1, 29); tf_round_c(x0, x1, 16); tf_round_c(x0, x1, 24);
    x0 += k1; x1 += k2 + 4u;
    tf_round_c(x0, x1, 13); tf_round_c(x0, x1, 15); tf_round_c(x0, x1, 26); tf_round_c(x0, x1, 6);
    x0 += k2; x1 += k0 + 5u;
    return make_uint2(x0, x1);
}

// Hot-loop round: the add is forced onto the IMAD (fma) pipe via the opaque
// multiplier `one` (a runtime kernel parameter ptxas cannot fold).
__device__ __forceinline__ void tf_round_h(uint32_t& x0, uint32_t& x1, int r,
                                           uint32_t one) {
    uint32_t t;
    asm("mad.lo.u32 %0, %1, %2, %3;" : "=r"(t) : "r"(x1), "r"(one), "r"(x0));
    x0 = t;
    x1 = __funnelshift_l(x1, x1, r);
    x1 ^= x0;
}

__device__ __forceinline__ uint32_t threefry_fold_h(uint32_t k0, uint32_t k1,
                                                    uint32_t k2, uint32_t c1,
                                                    uint32_t one) {
    // counter = (0, c1); returns x0 ^ x1.
    uint32_t x0 = k0;          // c0 (=0) + k0
    uint32_t x1 = c1 + k1;
    tf_round_h(x0, x1, 13, one); tf_round_h(x0, x1, 15, one);
    tf_round_h(x0, x1, 26, one); tf_round_h(x0, x1, 6, one);
    x0 += k1; x1 += k2 + 1u;
    tf_round_h(x0, x1, 17, one); tf_round_h(x0, x1, 29, one);
    tf_round_h(x0, x1, 16, one); tf_round_h(x0, x1, 24, one);
    x0 += k2; x1 += k0 + 2u;
    tf_round_h(x0, x1, 13, one); tf_round_h(x0, x1, 15, one);
    tf_round_h(x0, x1, 26, one); tf_round_h(x0, x1, 6, one);
    x0 += k0; x1 += k1 + 3u;
    tf_round_h(x0, x1, 17, one); tf_round_h(x0, x1, 29, one);
    tf_round_h(x0, x1, 16, one); tf_round_h(x0, x1, 24, one);
    x0 += k1; x1 += k2 + 4u;
    tf_round_h(x0, x1, 13, one); tf_round_h(x0, x1, 15, one);
    tf_round_h(x0, x1, 26, one); tf_round_h(x0, x1, 6, one);
    x0 += k2; x1 += k0 + 5u;
    return x0 ^ x1;
}

// XLA ErfInv 32-bit (Giles). Returns erfinv(x).
__device__ __forceinline__ float erfinv_xla(float x) {
    float t = fmaf(-x, x, 1.0f);            // 1 - x^2
    float lg;
    asm("lg2.approx.f32 %0, %1;" : "=f"(lg) : "f"(t));
    float w = -0.6931471805599453f * lg;    // -ln(1-x^2)
    float p;
    if (w < 5.0f) {
        w -= 2.5f;
        p = 2.81022636e-08f;
        p = fmaf(p, w, 3.43273939e-07f);
        p = fmaf(p, w, -3.5233877e-06f);
        p = fmaf(p, w, -4.39150654e-06f);
        p = fmaf(p, w, 0.00021858087f);
        p = fmaf(p, w, -0.00125372503f);
        p = fmaf(p, w, -0.00417768164f);
        p = fmaf(p, w, 0.246640727f);
        p = fmaf(p, w, 1.50140941f);
    } else {
        float sw;
        asm("sqrt.approx.f32 %0, %1;" : "=f"(sw) : "f"(w));
        w = sw - 3.0f;
        p = -0.000200214257f;
        p = fmaf(p, w, 0.000100950558f);
        p = fmaf(p, w, 0.00134934322f);
        p = fmaf(p, w, -0.00367342844f);
        p = fmaf(p, w, 0.00573950773f);
        p = fmaf(p, w, -0.0076224613f);
        p = fmaf(p, w, 0.00943887047f);
        p = fmaf(p, w, 1.00167406f);
        p = fmaf(p, w, 2.83297682f);
    }
    return p * x;
}

__global__ void __launch_bounds__(NTHREADS, 3)
mc_softmax_kernel(const float* __restrict__ mean,
                  const float* __restrict__ var,
                  const int* __restrict__ d_ns,
                  float* __restrict__ out,
                  uint32_t one) {
    __shared__ uint2 skeys[MAX_SAMPLES];

    int ns = d_ns ? *d_ns : 400;
    if (ns > MAX_SAMPLES) ns = MAX_SAMPLES;

    int tid = threadIdx.x;
    for (int s = tid; s < ns; s += NTHREADS) {
        skeys[s] = threefry2x32_c(0u, 42u, 0u, (uint32_t)s);
    }
    __syncthreads();

    int warp = tid >> 5;
    int lane = tid & 31;
    int row = blockIdx.x * WARPS_PER_BLOCK + warp;
    int base = row * NCOLS + lane;

    const float LOG2E = 1.4426950408889634f;
    const float S2LOG2E = 1.41421356237309504880f * 1.4426950408889634f;
    const float LO = __int_as_float(0xBF7FFFFF);  // nextafter(-1, 0)

    float m2[KPL], s3[KPL], acc[KPL];
#pragma unroll
    for (int k = 0; k < KPL; k++) {
        int i = base + 32 * k;
        m2[k] = mean[i] * LOG2E;
        s3[k] = sqrtf(var[i]) * S2LOG2E;
        acc[k] = 0.0f;
    }

    for (int s = 0; s < ns; s++) {
        uint2 key = skeys[s];
        uint32_t k2 = key.x ^ key.y ^ 0x1BD11BDAu;
        float e[KPL];
        float part = 0.0f;
#pragma unroll
        for (int k = 0; k < KPL; k++) {
            uint32_t i = (uint32_t)(base + 32 * k);
            uint32_t bits = threefry_fold_h(key.x, key.y, k2, i, one);
            // mantissa: top 23 bits -> [1,2); shift done on fma pipe (umulhi).
            float f = __uint_as_float(__umulhi(bits, 0x00800000u) | 0x3F800000u)
                      - 1.0f;
            // u = f*2 + LO; fmax(LO, .) is redundant (f >= 0 => result >= LO).
            float u = fmaf(f, 2.0f, LO);
            float g = erfinv_xla(u);          // p * u
            float t = fmaf(g, s3[k], m2[k]);  // (mean + eps) * log2(e)
            float ev;
            asm("ex2.approx.f32 %0, %1;" : "=f"(ev) : "f"(t));
            e[k] = ev;
            part += ev;
        }
#pragma unroll
        for (int o = 16; o > 0; o >>= 1)
            part += __shfl_xor_sync(0xffffffffu, part, o);
        float rinv;
        asm("rcp.approx.f32 %0, %1;" : "=f"(rinv) : "f"(part));
#pragma unroll
        for (int k = 0; k < KPL; k++)
            acc[k] = fmaf(e[k], rinv, acc[k]);
    }

    float inv = 1.0f / (float)ns;
#pragma unroll
    for (int k = 0; k < KPL; k++)
        out[base + 32 * k] = acc[k] * inv;
}

extern "C" void kernel_launch(void* const* d_in, const int* in_sizes, int n_in,
                              void* d_out, int out_size) {
    const float* mean = (const float*)d_in[0];
    const float* var = (const float*)d_in[1];
    const int* ns = (n_in >= 3) ? (const int*)d_in[2] : nullptr;
    float* out = (float*)d_out;

    dim3 grid(NROWS / WARPS_PER_BLOCK);
    dim3 block(NTHREADS);
    mc_softmax_kernel<<<grid, block>>>(mean, var, ns, out, 1u);
}

// round 3
// speedup vs baseline: 1.1628x; 1.0667x over previous
#include <cuda_runtime.h>
#include <cstdint>

// ============================================================================
// Monte-Carlo E[softmax(mean + eps)], JAX threefry-partitionable bit-exact.
// R3: m2/s3 moved to shared memory (frees 32 regs -> 4 CTAs/SM);
//     all 30 threefry adds forced to IMAD (fma pipe) via opaque `one`;
//     erfinv tail made an explicitly rare branch.
// ============================================================================

#define NROWS 16384
#define NCOLS 512
#define WARPS_PER_BLOCK 8
#define NTHREADS (WARPS_PER_BLOCK * 32)
#define KPL 16
#define MAX_SAMPLES 512

// a + b on the IMAD (fma) pipe: a*one + b, `one` opaque to ptxas.
__device__ __forceinline__ uint32_t madd(uint32_t a, uint32_t b, uint32_t one) {
    uint32_t t;
    asm("mad.lo.u32 %0, %1, %2, %3;" : "=r"(t) : "r"(a), "r"(one), "r"(b));
    return t;
}

// Compile-time threefry for per-sample subkeys (amortized, per block).
__device__ __forceinline__ void tf_round_c(uint32_t& x0, uint32_t& x1, int r) {
    x0 += x1;
    x1 = __funnelshift_l(x1, x1, r);
    x1 ^= x0;
}
__device__ __forceinline__ uint2 threefry2x32_c(uint32_t k0, uint32_t k1,
                                                uint32_t c0, uint32_t c1) {
    uint32_t k2 = k0 ^ k1 ^ 0x1BD11BDAu;
    uint32_t x0 = c0 + k0;
    uint32_t x1 = c1 + k1;
    tf_round_c(x0,x1,13); tf_round_c(x0,x1,15); tf_round_c(x0,x1,26); tf_round_c(x0,x1,6);
    x0 += k1; x1 += k2 + 1u;
    tf_round_c(x0,x1,17); tf_round_c(x0,x1,29); tf_round_c(x0,x1,16); tf_round_c(x0,x1,24);
    x0 += k2; x1 += k0 + 2u;
    tf_round_c(x0,x1,13); tf_round_c(x0,x1,15); tf_round_c(x0,x1,26); tf_round_c(x0,x1,6);
    x0 += k0; x1 += k1 + 3u;
    tf_round_c(x0,x1,17); tf_round_c(x0,x1,29); tf_round_c(x0,x1,16); tf_round_c(x0,x1,24);
    x0 += k1; x1 += k2 + 4u;
    tf_round_c(x0,x1,13); tf_round_c(x0,x1,15); tf_round_c(x0,x1,26); tf_round_c(x0,x1,6);
    x0 += k2; x1 += k0 + 5u;
    return make_uint2(x0, x1);
}

// Hot fold: counter (0, c1); x1 passed pre-added (c1 + k1); returns x0^x1.
// All adds on IMAD; SHF+LOP3 remain the only alu-pipe ops.
#define TFR(r) { x0 = madd(x1, x0, one); \
                 x1 = __funnelshift_l(x1, x1, r) ^ x0; }
__device__ __forceinline__ uint32_t tf_fold(
    uint32_t k0, uint32_t k1, uint32_t k2,
    uint32_t i1, uint32_t i2, uint32_t i3, uint32_t i4, uint32_t i5,
    uint32_t x1, uint32_t one)
{
    uint32_t x0 = k0;
    TFR(13); TFR(15); TFR(26); TFR(6);
    x0 = madd(k1, x0, one); x1 = madd(i1, x1, one);   // i1 = k2+1
    TFR(17); TFR(29); TFR(16); TFR(24);
    x0 = madd(k2, x0, one); x1 = madd(i2, x1, one);   // i2 = k0+2
    TFR(13); TFR(15); TFR(26); TFR(6);
    x0 = madd(k0, x0, one); x1 = madd(i3, x1, one);   // i3 = k1+3
    TFR(17); TFR(29); TFR(16); TFR(24);
    x0 = madd(k1, x0, one); x1 = madd(i4, x1, one);   // i4 = k2+4
    TFR(13); TFR(15); TFR(26); TFR(6);
    x0 = madd(k2, x0, one); x1 = madd(i5, x1, one);   // i5 = k0+5
    return x0 ^ x1;
}

// XLA ErfInv (Giles). Main path unconditional; rare tail (P~0.34%/lane)
// overwrites under an unlikely branch.
__device__ __forceinline__ float erfinv_xla(float x) {
    float t = fmaf(-x, x, 1.0f);
    float lg;
    asm("lg2.approx.f32 %0, %1;" : "=f"(lg) : "f"(t));
    float w = -0.6931471805599453f * lg;
    float ww = w - 2.5f;
    float p = 2.81022636e-08f;
    p = fmaf(p, ww, 3.43273939e-07f);
    p = fmaf(p, ww, -3.5233877e-06f);
    p = fmaf(p, ww, -4.39150654e-06f);
    p = fmaf(p, ww, 0.00021858087f);
    p = fmaf(p, ww, -0.00125372503f);
    p = fmaf(p, ww, -0.00417768164f);
    p = fmaf(p, ww, 0.246640727f);
    p = fmaf(p, ww, 1.50140941f);
    if (__builtin_expect(!!(w >= 5.0f), 0)) {
        float sw;
        asm("sqrt.approx.f32 %0, %1;" : "=f"(sw) : "f"(w));
        float v = sw - 3.0f;
        p = -0.000200214257f;
        p = fmaf(p, v, 0.000100950558f);
        p = fmaf(p, v, 0.00134934322f);
        p = fmaf(p, v, -0.00367342844f);
        p = fmaf(p, v, 0.00573950773f);
        p = fmaf(p, v, -0.0076224613f);
        p = fmaf(p, v, 0.00943887047f);
        p = fmaf(p, v, 1.00167406f);
        p = fmaf(p, v, 2.83297682f);
    }
    return p * x;
}

__global__ void __launch_bounds__(NTHREADS, 4)
mc_softmax_kernel(const float* __restrict__ mean,
                  const float* __restrict__ var,
                  const int* __restrict__ d_ns,
                  float* __restrict__ out,
                  uint32_t one) {
    __shared__ float2 ms[KPL * NTHREADS];   // 32 KB: (m2, s3) per element
    __shared__ uint2 skeys[MAX_SAMPLES];    //  4 KB

    int ns = d_ns ? *d_ns : 400;
    if (ns > MAX_SAMPLES) ns = MAX_SAMPLES;

    int tid = threadIdx.x;
    for (int s = tid; s < ns; s += NTHREADS)
        skeys[s] = threefry2x32_c(0u, 42u, 0u, (uint32_t)s);

    int warp = tid >> 5;
    int lane = tid & 31;
    int row = blockIdx.x * WARPS_PER_BLOCK + warp;
    int base = row * NCOLS + lane;

    const float LOG2E = 1.4426950408889634f;
    const float S2LOG2E = 1.41421356237309504880f * 1.4426950408889634f;
    const float LO = __int_as_float(0xBF7FFFFF);  // nextafter(-1, 0)

    float acc[KPL];
#pragma unroll
    for (int k = 0; k < KPL; k++) {
        int i = base + 32 * k;
        float2 v;
        v.x = mean[i] * LOG2E;
        v.y = sqrtf(var[i]) * S2LOG2E;
        ms[k * NTHREADS + tid] = v;
        acc[k] = 0.0f;
    }
    __syncthreads();

    for (int s = 0; s < ns; s++) {
        uint2 key = skeys[s];
        uint32_t k0 = key.x, k1 = key.y;
        uint32_t k2 = k0 ^ k1 ^ 0x1BD11BDAu;
        uint32_t i1 = k2 + 1u, i2 = k0 + 2u, i3 = k1 + 3u,
                 i4 = k2 + 4u, i5 = k0 + 5u;
        uint32_t cb = (uint32_t)base + k1;  // x1_init = counter + k1

        float e[KPL];
        float part = 0.0f;
#pragma unroll
        for (int k = 0; k < KPL; k++) {
            uint32_t bits = tf_fold(k0, k1, k2, i1, i2, i3, i4, i5,
                                    cb + 32u * (uint32_t)k, one);
            // (bits >> 9) on the fma pipe via umulhi; OR mantissa -> [1,2).
            float f = __uint_as_float(__umulhi(bits, 0x00800000u) | 0x3F800000u)
                      - 1.0f;
            float u = fmaf(f, 2.0f, LO);      // fmax(LO,.) redundant: f >= 0
            float g = erfinv_xla(u);
            float2 msk = ms[k * NTHREADS + tid];
            float t = fmaf(g, msk.y, msk.x);  // (mean + eps) * log2(e)
            float ev;
            asm("ex2.approx.f32 %0, %1;" : "=f"(ev) : "f"(t));
            e[k] = ev;
            part += ev;
        }
#pragma unroll
        for (int o = 16; o > 0; o >>= 1)
            part += __shfl_xor_sync(0xffffffffu, part, o);
        float rinv;
        asm("rcp.approx.f32 %0, %1;" : "=f"(rinv) : "f"(part));
#pragma unroll
        for (int k = 0; k < KPL; k++)
            acc[k] = fmaf(e[k], rinv, acc[k]);
    }

    float inv = 1.0f / (float)ns;
#pragma unroll
    for (int k = 0; k < KPL; k++)
        out[base + 32 * k] = acc[k] * inv;
}

extern "C" void kernel_launch(void* const* d_in, const int* in_sizes, int n_in,
                              void* d_out, int out_size) {
    const float* mean = (const float*)d_in[0];
    const float* var = (const float*)d_in[1];
    const int* ns = (n_in >= 3) ? (const int*)d_in[2] : nullptr;
    float* out = (float*)d_out;

    dim3 grid(NROWS / WARPS_PER_BLOCK);
    dim3 block(NTHREADS);
    mc_softmax_kernel<<<grid, block>>>(mean, var, ns, out, 1u);
}